// round 13
// baseline (speedup 1.0000x reference)
#include <cuda_runtime.h>
#include <cuda_fp16.h>

#define N_NODES 100000
#define IN_F    128
#define OUT_F   64
#define E_MAX   1600000

#define SCAN_B  1024
#define N_SCANB ((N_NODES + SCAN_B - 1) / SCAN_B)   // 98

// ------------------------- device scratch (no allocs) -----------------------
__device__ int   g_deg [N_NODES];       // zeroed by hop2 each run (zero-init at load)
__device__ int   g_bsum[N_SCANB];       // block aggregates; -1 = not published
__device__ int   g_off [N_NODES];       // row start; fill bumps it to row end
__device__ int   g_adj [E_MAX];
__device__ float g_norm[N_NODES];
__device__ float g_nsq [N_NODES];
// fp16 rows: 64 halves = 8 uint4 per node (128B)
__device__ uint4 g_gh [N_NODES * 8];    // g0 = feat@W^T (un-normalized)
__device__ uint4 g_g1 [N_NODES * 8];    // g1 = norm[s] * g0[s]
__device__ uint4 g_h1h[N_NODES * 8];    // X[n] = nsq[n] * sum_s g1[s]

// ------------------------- packed f32x2 helpers (Blackwell FFMA2) -----------
__device__ __forceinline__ unsigned long long pk2(float lo, float hi) {
    unsigned long long r;
    asm("mov.b64 %0, {%1, %2};" : "=l"(r) : "f"(lo), "f"(hi));
    return r;
}
__device__ __forceinline__ unsigned long long fma2(unsigned long long a,
                                                   unsigned long long b,
                                                   unsigned long long c) {
    unsigned long long d;
    asm("fma.rn.f32x2 %0, %1, %2, %3;" : "=l"(d) : "l"(a), "l"(b), "l"(c));
    return d;
}
__device__ __forceinline__ float2 upk2(unsigned long long v) {
    float2 f;
    asm("mov.b64 {%0, %1}, %2;" : "=f"(f.x), "=f"(f.y) : "l"(v));
    return f;
}

// ------------------------- degree histogram (+ bsum sentinel reset) ---------
__global__ void deg_kernel(const int* __restrict__ dst, int E) {
    int t = blockIdx.x * blockDim.x + threadIdx.x;
    if (t < N_SCANB) g_bsum[t] = -1;        // sentinels (read only by scan)
    int i = t * 4;
    if (i + 3 < E) {
        int4 d = *(const int4*)(dst + i);
        atomicAdd(&g_deg[d.x], 1);
        atomicAdd(&g_deg[d.y], 1);
        atomicAdd(&g_deg[d.z], 1);
        atomicAdd(&g_deg[d.w], 1);
    } else {
        for (int k = i; k < E; k++) atomicAdd(&g_deg[dst[k]], 1);
    }
}

// ------------------------- fused scan (lookback) + norm ----------------------
__global__ void scan_kernel() {
    __shared__ int wsum[32];
    __shared__ int s_prefix;
    int tid  = threadIdx.x;
    int lane = tid & 31;
    int wid  = tid >> 5;
    int b    = blockIdx.x;
    int i    = b * SCAN_B + tid;
    int v    = (i < N_NODES) ? g_deg[i] : 0;

    if (i < N_NODES) {
        float nv = (v > 0) ? rsqrtf((float)v) : 0.0f;
        g_norm[i] = nv;
        g_nsq[i]  = nv * nv;
    }

    int x = v;
#pragma unroll
    for (int o = 1; o < 32; o <<= 1) {
        int t = __shfl_up_sync(0xffffffffu, x, o);
        if (lane >= o) x += t;
    }
    if (lane == 31) wsum[wid] = x;
    __syncthreads();
    if (wid == 0) {
        int w = wsum[lane];
#pragma unroll
        for (int o = 1; o < 32; o <<= 1) {
            int t = __shfl_up_sync(0xffffffffu, w, o);
            if (lane >= o) w += t;
        }
        wsum[lane] = w;
    }
    __syncthreads();
    int incl = x + (wid > 0 ? wsum[wid - 1] : 0);

    if (tid == SCAN_B - 1) atomicExch(&g_bsum[b], incl);

    if (wid == 0) {
        int acc = 0;
        for (int t = lane; t < b; t += 32) {
            int val;
            do { val = atomicAdd(&g_bsum[t], 0); } while (val == -1);
            acc += val;
        }
#pragma unroll
        for (int o = 16; o > 0; o >>= 1)
            acc += __shfl_xor_sync(0xffffffffu, acc, o);
        if (lane == 0) s_prefix = acc;
    }
    __syncthreads();

    if (i < N_NODES) g_off[i] = s_prefix + incl - v;   // row start (= fill cursor)
}

// ------------------------- CSR fill: 1 edge/thread (max latency hiding) ----
__global__ void fill_kernel(const int* __restrict__ src,
                            const int* __restrict__ dst, int E) {
    int e = blockIdx.x * blockDim.x + threadIdx.x;
    if (e < E) {
        int pos = atomicAdd(&g_off[dst[e]], 1);
        g_adj[pos] = src[e];
    }
}

// ------------------------- dense GEMM: g0 = feat @ W^T (fp16 out) ------------
// Inner product via packed fma.rn.f32x2: 8 FFMA2 per k instead of 16 FFMA.
#define KP 68
__global__ void gemm_kernel(const float* __restrict__ feat,
                            const float* __restrict__ weight) {
    __shared__ float Ws[IN_F * KP];
    __shared__ float Fs[32 * KP];

    int tid = threadIdx.x;
    for (int p = tid; p < OUT_F * 32; p += 256) {
        int out = p >> 5, jc = p & 31;
        float4 w = ((const float4*)weight)[out * 32 + jc];
        int k = jc * 4;
        Ws[(k + 0) * KP + out] = w.x;
        Ws[(k + 1) * KP + out] = w.y;
        Ws[(k + 2) * KP + out] = w.z;
        Ws[(k + 3) * KP + out] = w.w;
    }

    int nodeBase = blockIdx.x * 64;
    int tx = tid & 15;
    int ty = tid >> 4;
    unsigned long long acc2[4][2] = {};   // [node][out-pair], f32x2 packed

    for (int kc = 0; kc < IN_F; kc += 32) {
        __syncthreads();
        for (int p = tid; p < 64 * 8; p += 256) {
            int n = p >> 3, jc = p & 7;
            int node = nodeBase + n;
            float4 f = (node < N_NODES)
                ? ((const float4*)feat)[node * 32 + (kc >> 2) + jc]
                : make_float4(0.f, 0.f, 0.f, 0.f);
            int k = jc * 4;
            Fs[(k + 0) * KP + n] = f.x;
            Fs[(k + 1) * KP + n] = f.y;
            Fs[(k + 2) * KP + n] = f.z;
            Fs[(k + 3) * KP + n] = f.w;
        }
        __syncthreads();
#pragma unroll
        for (int k = 0; k < 32; k++) {
            float4 fv = *(const float4*)&Fs[k * KP + ty * 4];
            float4 wv = *(const float4*)&Ws[(kc + k) * KP + tx * 4];
            unsigned long long wp0 = pk2(wv.x, wv.y);
            unsigned long long wp1 = pk2(wv.z, wv.w);
            float f[4] = {fv.x, fv.y, fv.z, fv.w};
#pragma unroll
            for (int i = 0; i < 4; i++) {
                unsigned long long ff = pk2(f[i], f[i]);
                acc2[i][0] = fma2(ff, wp0, acc2[i][0]);
                acc2[i][1] = fma2(ff, wp1, acc2[i][1]);
            }
        }
    }

    uint2* out2 = (uint2*)g_gh;
#pragma unroll
    for (int i = 0; i < 4; i++) {
        int node = nodeBase + ty * 4 + i;
        if (node < N_NODES) {
            float2 p0 = upk2(acc2[i][0]);
            float2 p1 = upk2(acc2[i][1]);
            __half2 h0 = __floats2half2_rn(p0.x, p0.y);
            __half2 h1 = __floats2half2_rn(p1.x, p1.y);
            uint2 u;
            u.x = *(unsigned int*)&h0;
            u.y = *(unsigned int*)&h1;
            out2[node * 16 + tx] = u;
        }
    }
}

// ------------------------- scale: g1 = norm[node] * g0 (on s2, hidden) ------
__global__ void scale_kernel() {
    int idx = blockIdx.x * blockDim.x + threadIdx.x;
    if (idx >= N_NODES * 8) return;
    int node = idx >> 3;
    float nv = g_norm[node];
    uint4 v = g_gh[idx];
    float2 f;
    __half2 h;
    f = __half22float2(*reinterpret_cast<__half2*>(&v.x));
    h = __floats2half2_rn(f.x * nv, f.y * nv); v.x = *(unsigned*)&h;
    f = __half22float2(*reinterpret_cast<__half2*>(&v.y));
    h = __floats2half2_rn(f.x * nv, f.y * nv); v.y = *(unsigned*)&h;
    f = __half22float2(*reinterpret_cast<__half2*>(&v.z));
    h = __floats2half2_rn(f.x * nv, f.y * nv); v.z = *(unsigned*)&h;
    f = __half22float2(*reinterpret_cast<__half2*>(&v.w));
    h = __floats2half2_rn(f.x * nv, f.y * nv); v.w = *(unsigned*)&h;
    __stcg(&g_g1[idx], v);
}

// ------------------------- gather hops: warp/node, 4 phases x uint4 ---------
__device__ __forceinline__ void u4acc(uint4 v, float2* a) {
    float2 f;
    f = __half22float2(*reinterpret_cast<__half2*>(&v.x)); a[0].x += f.x; a[0].y += f.y;
    f = __half22float2(*reinterpret_cast<__half2*>(&v.y)); a[1].x += f.x; a[1].y += f.y;
    f = __half22float2(*reinterpret_cast<__half2*>(&v.z)); a[2].x += f.x; a[2].y += f.y;
    f = __half22float2(*reinterpret_cast<__half2*>(&v.w)); a[3].x += f.x; a[3].y += f.y;
}

__device__ __forceinline__ void phase_reduce(float2* a) {
#pragma unroll
    for (int q = 0; q < 4; q++) {
        a[q].x += __shfl_xor_sync(0xffffffffu, a[q].x, 8);
        a[q].y += __shfl_xor_sync(0xffffffffu, a[q].y, 8);
        a[q].x += __shfl_xor_sync(0xffffffffu, a[q].x, 16);
        a[q].y += __shfl_xor_sync(0xffffffffu, a[q].y, 16);
    }
}

// hop1: X[n] = nsq[n] * sum_s g1[s]
__global__ void __launch_bounds__(512, 4) hop1_kernel() {
    int node = (blockIdx.x * blockDim.x + threadIdx.x) >> 5;
    if (node >= N_NODES) return;
    int lane = threadIdx.x & 31;
    int j  = lane & 7;
    int ph = lane >> 3;

    int cnt   = g_deg[node];
    int start = g_off[node] - cnt;     // g_off was bumped to row end by fill

    float2 a[4] = {{0,0},{0,0},{0,0},{0,0}};
    int i = ph;
    for (; i + 12 < cnt; i += 16) {
        int s0 = __ldg(&g_adj[start + i]);
        int s1 = __ldg(&g_adj[start + i + 4]);
        int s2 = __ldg(&g_adj[start + i + 8]);
        int s3 = __ldg(&g_adj[start + i + 12]);
        uint4 v0 = __ldcg(&g_g1[s0 * 8 + j]);
        uint4 v1 = __ldcg(&g_g1[s1 * 8 + j]);
        uint4 v2 = __ldcg(&g_g1[s2 * 8 + j]);
        uint4 v3 = __ldcg(&g_g1[s3 * 8 + j]);
        u4acc(v0, a); u4acc(v1, a); u4acc(v2, a); u4acc(v3, a);
    }
    if (i + 8 < cnt) {
        int s0 = __ldg(&g_adj[start + i]);
        int s1 = __ldg(&g_adj[start + i + 4]);
        int s2 = __ldg(&g_adj[start + i + 8]);
        uint4 v0 = __ldcg(&g_g1[s0 * 8 + j]);
        uint4 v1 = __ldcg(&g_g1[s1 * 8 + j]);
        uint4 v2 = __ldcg(&g_g1[s2 * 8 + j]);
        u4acc(v0, a); u4acc(v1, a); u4acc(v2, a);
    } else if (i + 4 < cnt) {
        int s0 = __ldg(&g_adj[start + i]);
        int s1 = __ldg(&g_adj[start + i + 4]);
        uint4 v0 = __ldcg(&g_g1[s0 * 8 + j]);
        uint4 v1 = __ldcg(&g_g1[s1 * 8 + j]);
        u4acc(v0, a); u4acc(v1, a);
    } else if (i < cnt) {
        int s0 = __ldg(&g_adj[start + i]);
        u4acc(__ldcg(&g_g1[s0 * 8 + j]), a);
    }
    phase_reduce(a);
    if (ph == 0) {
        float sc = g_nsq[node];
        __half2 h0 = __floats2half2_rn(a[0].x * sc, a[0].y * sc);
        __half2 h1 = __floats2half2_rn(a[1].x * sc, a[1].y * sc);
        __half2 h2 = __floats2half2_rn(a[2].x * sc, a[2].y * sc);
        __half2 h3 = __floats2half2_rn(a[3].x * sc, a[3].y * sc);
        uint4 u;
        u.x = *(unsigned int*)&h0;
        u.y = *(unsigned int*)&h1;
        u.z = *(unsigned int*)&h2;
        u.w = *(unsigned int*)&h3;
        __stcg(&g_h1h[node * 8 + j], u);
    }
}

// hop2: out[n] = norm[n] * sum_s X[s] + bias ; also re-zeroes g_deg for the
// next graph replay (device globals are zero-init at load, so run 1 is fine).
__global__ void __launch_bounds__(512, 4) hop2_kernel(float* __restrict__ out,
                                                      const float* __restrict__ bias) {
    int node = (blockIdx.x * blockDim.x + threadIdx.x) >> 5;
    if (node >= N_NODES) return;
    int lane = threadIdx.x & 31;
    int j  = lane & 7;
    int ph = lane >> 3;

    int cnt   = g_deg[node];
    int start = g_off[node] - cnt;
    if (lane == 0) g_deg[node] = 0;    // sole reader of this counter; safe

    float2 a[4] = {{0,0},{0,0},{0,0},{0,0}};
    int i = ph;
    for (; i + 12 < cnt; i += 16) {
        int s0 = __ldg(&g_adj[start + i]);
        int s1 = __ldg(&g_adj[start + i + 4]);
        int s2 = __ldg(&g_adj[start + i + 8]);
        int s3 = __ldg(&g_adj[start + i + 12]);
        uint4 v0 = __ldcg(&g_h1h[s0 * 8 + j]);
        uint4 v1 = __ldcg(&g_h1h[s1 * 8 + j]);
        uint4 v2 = __ldcg(&g_h1h[s2 * 8 + j]);
        uint4 v3 = __ldcg(&g_h1h[s3 * 8 + j]);
        u4acc(v0, a); u4acc(v1, a); u4acc(v2, a); u4acc(v3, a);
    }
    if (i + 8 < cnt) {
        int s0 = __ldg(&g_adj[start + i]);
        int s1 = __ldg(&g_adj[start + i + 4]);
        int s2 = __ldg(&g_adj[start + i + 8]);
        uint4 v0 = __ldcg(&g_h1h[s0 * 8 + j]);
        uint4 v1 = __ldcg(&g_h1h[s1 * 8 + j]);
        uint4 v2 = __ldcg(&g_h1h[s2 * 8 + j]);
        u4acc(v0, a); u4acc(v1, a); u4acc(v2, a);
    } else if (i + 4 < cnt) {
        int s0 = __ldg(&g_adj[start + i]);
        int s1 = __ldg(&g_adj[start + i + 4]);
        uint4 v0 = __ldcg(&g_h1h[s0 * 8 + j]);
        uint4 v1 = __ldcg(&g_h1h[s1 * 8 + j]);
        u4acc(v0, a); u4acc(v1, a);
    } else if (i < cnt) {
        int s0 = __ldg(&g_adj[start + i]);
        u4acc(__ldcg(&g_h1h[s0 * 8 + j]), a);
    }
    phase_reduce(a);
    if (ph == 0) {
        float sc = g_norm[node];
        const float4* b4 = (const float4*)bias;
        float4 b0 = b4[j * 2], b1 = b4[j * 2 + 1];
        float4 o0, o1;
        o0.x = a[0].x * sc + b0.x;  o0.y = a[0].y * sc + b0.y;
        o0.z = a[1].x * sc + b0.z;  o0.w = a[1].y * sc + b0.w;
        o1.x = a[2].x * sc + b1.x;  o1.y = a[2].y * sc + b1.y;
        o1.z = a[3].x * sc + b1.z;  o1.w = a[3].y * sc + b1.w;
        float4* out4 = (float4*)out;
        out4[node * 16 + j * 2]     = o0;
        out4[node * 16 + j * 2 + 1] = o1;
    }
}

// ----------------------------------------------------------------------------
extern "C" void kernel_launch(void* const* d_in, const int* in_sizes, int n_in,
                              void* d_out, int out_size) {
    const int*   src    = (const int*)  d_in[0];
    const int*   dst    = (const int*)  d_in[1];
    const float* feat   = (const float*)d_in[2];
    const float* weight = (const float*)d_in[3];
    const float* bias   = (const float*)d_in[4];
    float*       out    = (float*)d_out;

    const int E = in_sizes[0];

    static cudaStream_t s2 = nullptr;
    static cudaEvent_t ev_fork = nullptr, ev_scan = nullptr, ev_join = nullptr;
    if (!s2) {
        cudaStreamCreateWithFlags(&s2, cudaStreamNonBlocking);
        cudaEventCreateWithFlags(&ev_fork, cudaEventDisableTiming);
        cudaEventCreateWithFlags(&ev_scan, cudaEventDisableTiming);
        cudaEventCreateWithFlags(&ev_join, cudaEventDisableTiming);
    }

    // Fork GEMM immediately (no dependencies). No memsets: g_deg is zeroed
    // by the previous run's hop2 (and zero-initialized at module load).
    cudaEventRecord(ev_fork, 0);
    cudaStreamWaitEvent(s2, ev_fork, 0);
    gemm_kernel<<<(N_NODES + 63) / 64, 256, 0, s2>>>(feat, weight);

    deg_kernel<<<(E / 4 + 255) / 256, 256>>>(dst, E);   // also sets bsum=-1
    scan_kernel<<<N_SCANB, SCAN_B>>>();                  // norm + row offsets

    // scale needs norm (scan, s0) + g0 (gemm, same stream); hidden behind fill
    cudaEventRecord(ev_scan, 0);
    cudaStreamWaitEvent(s2, ev_scan, 0);
    scale_kernel<<<(N_NODES * 8 + 255) / 256, 256, 0, s2>>>();
    cudaEventRecord(ev_join, s2);

    fill_kernel<<<(E + 255) / 256, 256>>>(src, dst, E);

    cudaStreamWaitEvent(0, ev_join, 0);

    int hop_threads = N_NODES * 32;
    int hop_blocks  = (hop_threads + 511) / 512;
    hop1_kernel<<<hop_blocks, 512>>>();
    hop2_kernel<<<hop_blocks, 512>>>(out, bias);
}

// round 15
// speedup vs baseline: 1.6367x; 1.6367x over previous
#include <cuda_runtime.h>
#include <cuda_fp16.h>

#define N_NODES 100000
#define IN_F    128
#define OUT_F   64
#define E_MAX   1600000

#define SCAN_B  1024
#define N_SCANB ((N_NODES + SCAN_B - 1) / SCAN_B)   // 98

// ------------------------- device scratch (no allocs) -----------------------
__device__ int   g_deg [N_NODES];
__device__ int   g_bsum[N_SCANB];       // block aggregates; -1 = not published
__device__ int   g_off [N_NODES];       // row start; fill bumps it to row end
__device__ int   g_adj [E_MAX];
__device__ float g_norm[N_NODES];
__device__ float g_nsq [N_NODES];
// fp16 rows: 64 halves = 8 uint4 per node (128B)
__device__ uint4 g_gh [N_NODES * 8];    // g0 = feat@W^T (un-normalized)
__device__ uint4 g_g1 [N_NODES * 8];    // g1 = norm[s] * g0[s]
__device__ uint4 g_h1h[N_NODES * 8];    // X[n] = nsq[n] * sum_s g1[s]

// ------------------------- degree histogram (+ bsum sentinel reset) ---------
__global__ void deg_kernel(const int* __restrict__ dst, int E) {
    int t = blockIdx.x * blockDim.x + threadIdx.x;
    if (t < N_SCANB) g_bsum[t] = -1;        // sentinels (read only by scan)
    int i = t * 4;
    if (i + 3 < E) {
        int4 d = *(const int4*)(dst + i);
        atomicAdd(&g_deg[d.x], 1);
        atomicAdd(&g_deg[d.y], 1);
        atomicAdd(&g_deg[d.z], 1);
        atomicAdd(&g_deg[d.w], 1);
    } else {
        for (int k = i; k < E; k++) atomicAdd(&g_deg[dst[k]], 1);
    }
}

// ------------------------- fused scan (lookback) + norm ----------------------
__global__ void scan_kernel() {
    __shared__ int wsum[32];
    __shared__ int s_prefix;
    int tid  = threadIdx.x;
    int lane = tid & 31;
    int wid  = tid >> 5;
    int b    = blockIdx.x;
    int i    = b * SCAN_B + tid;
    int v    = (i < N_NODES) ? g_deg[i] : 0;

    if (i < N_NODES) {
        float nv = (v > 0) ? rsqrtf((float)v) : 0.0f;
        g_norm[i] = nv;
        g_nsq[i]  = nv * nv;
    }

    int x = v;
#pragma unroll
    for (int o = 1; o < 32; o <<= 1) {
        int t = __shfl_up_sync(0xffffffffu, x, o);
        if (lane >= o) x += t;
    }
    if (lane == 31) wsum[wid] = x;
    __syncthreads();
    if (wid == 0) {
        int w = wsum[lane];
#pragma unroll
        for (int o = 1; o < 32; o <<= 1) {
            int t = __shfl_up_sync(0xffffffffu, w, o);
            if (lane >= o) w += t;
        }
        wsum[lane] = w;
    }
    __syncthreads();
    int incl = x + (wid > 0 ? wsum[wid - 1] : 0);

    if (tid == SCAN_B - 1) atomicExch(&g_bsum[b], incl);

    if (wid == 0) {
        int acc = 0;
        for (int t = lane; t < b; t += 32) {
            int val;
            do { val = atomicAdd(&g_bsum[t], 0); } while (val == -1);
            acc += val;
        }
#pragma unroll
        for (int o = 16; o > 0; o >>= 1)
            acc += __shfl_xor_sync(0xffffffffu, acc, o);
        if (lane == 0) s_prefix = acc;
    }
    __syncthreads();

    if (i < N_NODES) g_off[i] = s_prefix + incl - v;   // row start (= fill cursor)
}

// ------------------------- CSR fill: 1 edge/thread (max latency hiding) ----
__global__ void fill_kernel(const int* __restrict__ src,
                            const int* __restrict__ dst, int E) {
    int e = blockIdx.x * blockDim.x + threadIdx.x;
    if (e < E) {
        int pos = atomicAdd(&g_off[dst[e]], 1);
        g_adj[pos] = src[e];
    }
}

// ------------------------- dense GEMM: g0 = feat @ W^T (fp16 out) ------------
// 128 nodes x 64 outs per block; 256 threads; 4x8 micro-tile.
// Dynamic smem (50.5 KB > 48 KB static limit; attribute set host-side).
#define KP 68
#define FP 132
#define GEMM_SMEM_BYTES ((IN_F * KP + 32 * FP) * 4)
__global__ void gemm_kernel(const float* __restrict__ feat,
                            const float* __restrict__ weight) {
    extern __shared__ float smem[];
    float* Ws = smem;                 // Ws[k][out], IN_F*KP
    float* Fs = smem + IN_F * KP;     // Fs[k][node], 32*FP

    int tid = threadIdx.x;
    for (int p = tid; p < OUT_F * 32; p += 256) {
        int out = p >> 5, jc = p & 31;
        float4 w = ((const float4*)weight)[out * 32 + jc];
        int k = jc * 4;
        Ws[(k + 0) * KP + out] = w.x;
        Ws[(k + 1) * KP + out] = w.y;
        Ws[(k + 2) * KP + out] = w.z;
        Ws[(k + 3) * KP + out] = w.w;
    }

    int nodeBase = blockIdx.x * 128;
    int tx = tid & 7;        // out group: outs tx*8 .. tx*8+7
    int ty = tid >> 3;       // node group: nodes ty*4 .. ty*4+3 (0..31)
    float acc[4][8] = {};

    for (int kc = 0; kc < IN_F; kc += 32) {
        __syncthreads();
        for (int p = tid; p < 128 * 8; p += 256) {
            int n = p >> 3, jc = p & 7;
            int node = nodeBase + n;
            float4 f = (node < N_NODES)
                ? ((const float4*)feat)[node * 32 + (kc >> 2) + jc]
                : make_float4(0.f, 0.f, 0.f, 0.f);
            int k = jc * 4;
            Fs[(k + 0) * FP + n] = f.x;
            Fs[(k + 1) * FP + n] = f.y;
            Fs[(k + 2) * FP + n] = f.z;
            Fs[(k + 3) * FP + n] = f.w;
        }
        __syncthreads();
#pragma unroll 8
        for (int k = 0; k < 32; k++) {
            float4 fv = *(const float4*)&Fs[k * FP + ty * 4];
            float4 w0 = *(const float4*)&Ws[(kc + k) * KP + tx * 8];
            float4 w1 = *(const float4*)&Ws[(kc + k) * KP + tx * 8 + 4];
            float f[4] = {fv.x, fv.y, fv.z, fv.w};
            float w[8] = {w0.x, w0.y, w0.z, w0.w, w1.x, w1.y, w1.z, w1.w};
#pragma unroll
            for (int i = 0; i < 4; i++)
#pragma unroll
                for (int j = 0; j < 8; j++)
                    acc[i][j] += f[i] * w[j];
        }
    }

#pragma unroll
    for (int i = 0; i < 4; i++) {
        int node = nodeBase + ty * 4 + i;
        if (node < N_NODES) {
            __half2 h0 = __floats2half2_rn(acc[i][0], acc[i][1]);
            __half2 h1 = __floats2half2_rn(acc[i][2], acc[i][3]);
            __half2 h2 = __floats2half2_rn(acc[i][4], acc[i][5]);
            __half2 h3 = __floats2half2_rn(acc[i][6], acc[i][7]);
            uint4 u;
            u.x = *(unsigned int*)&h0;
            u.y = *(unsigned int*)&h1;
            u.z = *(unsigned int*)&h2;
            u.w = *(unsigned int*)&h3;
            g_gh[node * 8 + tx] = u;
        }
    }
}

// ------------------------- scale: g1 = norm[node] * g0 (on s2, hidden) ------
__global__ void scale_kernel() {
    int idx = blockIdx.x * blockDim.x + threadIdx.x;
    if (idx >= N_NODES * 8) return;
    int node = idx >> 3;
    float nv = g_norm[node];
    uint4 v = g_gh[idx];
    float2 f;
    __half2 h;
    f = __half22float2(*reinterpret_cast<__half2*>(&v.x));
    h = __floats2half2_rn(f.x * nv, f.y * nv); v.x = *(unsigned*)&h;
    f = __half22float2(*reinterpret_cast<__half2*>(&v.y));
    h = __floats2half2_rn(f.x * nv, f.y * nv); v.y = *(unsigned*)&h;
    f = __half22float2(*reinterpret_cast<__half2*>(&v.z));
    h = __floats2half2_rn(f.x * nv, f.y * nv); v.z = *(unsigned*)&h;
    f = __half22float2(*reinterpret_cast<__half2*>(&v.w));
    h = __floats2half2_rn(f.x * nv, f.y * nv); v.w = *(unsigned*)&h;
    __stcg(&g_g1[idx], v);
}

// ------------------------- gather hops: warp/node, 4 phases x uint4 ---------
__device__ __forceinline__ void u4acc(uint4 v, float2* a) {
    float2 f;
    f = __half22float2(*reinterpret_cast<__half2*>(&v.x)); a[0].x += f.x; a[0].y += f.y;
    f = __half22float2(*reinterpret_cast<__half2*>(&v.y)); a[1].x += f.x; a[1].y += f.y;
    f = __half22float2(*reinterpret_cast<__half2*>(&v.z)); a[2].x += f.x; a[2].y += f.y;
    f = __half22float2(*reinterpret_cast<__half2*>(&v.w)); a[3].x += f.x; a[3].y += f.y;
}

__device__ __forceinline__ void phase_reduce(float2* a) {
#pragma unroll
    for (int q = 0; q < 4; q++) {
        a[q].x += __shfl_xor_sync(0xffffffffu, a[q].x, 8);
        a[q].y += __shfl_xor_sync(0xffffffffu, a[q].y, 8);
        a[q].x += __shfl_xor_sync(0xffffffffu, a[q].x, 16);
        a[q].y += __shfl_xor_sync(0xffffffffu, a[q].y, 16);
    }
}

// hop1: X[n] = nsq[n] * sum_s g1[s]
__global__ void __launch_bounds__(512, 4) hop1_kernel() {
    int node = (blockIdx.x * blockDim.x + threadIdx.x) >> 5;
    if (node >= N_NODES) return;
    int lane = threadIdx.x & 31;
    int j  = lane & 7;
    int ph = lane >> 3;

    int cnt   = g_deg[node];
    int start = g_off[node] - cnt;     // g_off was bumped to row end by fill

    float2 a[4] = {{0,0},{0,0},{0,0},{0,0}};
    int i = ph;
    for (; i + 12 < cnt; i += 16) {
        int s0 = __ldg(&g_adj[start + i]);
        int s1 = __ldg(&g_adj[start + i + 4]);
        int s2 = __ldg(&g_adj[start + i + 8]);
        int s3 = __ldg(&g_adj[start + i + 12]);
        uint4 v0 = __ldcg(&g_g1[s0 * 8 + j]);
        uint4 v1 = __ldcg(&g_g1[s1 * 8 + j]);
        uint4 v2 = __ldcg(&g_g1[s2 * 8 + j]);
        uint4 v3 = __ldcg(&g_g1[s3 * 8 + j]);
        u4acc(v0, a); u4acc(v1, a); u4acc(v2, a); u4acc(v3, a);
    }
    if (i + 8 < cnt) {
        int s0 = __ldg(&g_adj[start + i]);
        int s1 = __ldg(&g_adj[start + i + 4]);
        int s2 = __ldg(&g_adj[start + i + 8]);
        uint4 v0 = __ldcg(&g_g1[s0 * 8 + j]);
        uint4 v1 = __ldcg(&g_g1[s1 * 8 + j]);
        uint4 v2 = __ldcg(&g_g1[s2 * 8 + j]);
        u4acc(v0, a); u4acc(v1, a); u4acc(v2, a);
    } else if (i + 4 < cnt) {
        int s0 = __ldg(&g_adj[start + i]);
        int s1 = __ldg(&g_adj[start + i + 4]);
        uint4 v0 = __ldcg(&g_g1[s0 * 8 + j]);
        uint4 v1 = __ldcg(&g_g1[s1 * 8 + j]);
        u4acc(v0, a); u4acc(v1, a);
    } else if (i < cnt) {
        int s0 = __ldg(&g_adj[start + i]);
        u4acc(__ldcg(&g_g1[s0 * 8 + j]), a);
    }
    phase_reduce(a);
    if (ph == 0) {
        float sc = g_nsq[node];
        __half2 h0 = __floats2half2_rn(a[0].x * sc, a[0].y * sc);
        __half2 h1 = __floats2half2_rn(a[1].x * sc, a[1].y * sc);
        __half2 h2 = __floats2half2_rn(a[2].x * sc, a[2].y * sc);
        __half2 h3 = __floats2half2_rn(a[3].x * sc, a[3].y * sc);
        uint4 u;
        u.x = *(unsigned int*)&h0;
        u.y = *(unsigned int*)&h1;
        u.z = *(unsigned int*)&h2;
        u.w = *(unsigned int*)&h3;
        __stcg(&g_h1h[node * 8 + j], u);
    }
}

// hop2: out[n] = norm[n] * sum_s X[s] + bias
__global__ void __launch_bounds__(512, 4) hop2_kernel(float* __restrict__ out,
                                                      const float* __restrict__ bias) {
    int node = (blockIdx.x * blockDim.x + threadIdx.x) >> 5;
    if (node >= N_NODES) return;
    int lane = threadIdx.x & 31;
    int j  = lane & 7;
    int ph = lane >> 3;

    int cnt   = g_deg[node];
    int start = g_off[node] - cnt;

    float2 a[4] = {{0,0},{0,0},{0,0},{0,0}};
    int i = ph;
    for (; i + 12 < cnt; i += 16) {
        int s0 = __ldg(&g_adj[start + i]);
        int s1 = __ldg(&g_adj[start + i + 4]);
        int s2 = __ldg(&g_adj[start + i + 8]);
        int s3 = __ldg(&g_adj[start + i + 12]);
        uint4 v0 = __ldcg(&g_h1h[s0 * 8 + j]);
        uint4 v1 = __ldcg(&g_h1h[s1 * 8 + j]);
        uint4 v2 = __ldcg(&g_h1h[s2 * 8 + j]);
        uint4 v3 = __ldcg(&g_h1h[s3 * 8 + j]);
        u4acc(v0, a); u4acc(v1, a); u4acc(v2, a); u4acc(v3, a);
    }
    if (i + 8 < cnt) {
        int s0 = __ldg(&g_adj[start + i]);
        int s1 = __ldg(&g_adj[start + i + 4]);
        int s2 = __ldg(&g_adj[start + i + 8]);
        uint4 v0 = __ldcg(&g_h1h[s0 * 8 + j]);
        uint4 v1 = __ldcg(&g_h1h[s1 * 8 + j]);
        uint4 v2 = __ldcg(&g_h1h[s2 * 8 + j]);
        u4acc(v0, a); u4acc(v1, a); u4acc(v2, a);
    } else if (i + 4 < cnt) {
        int s0 = __ldg(&g_adj[start + i]);
        int s1 = __ldg(&g_adj[start + i + 4]);
        uint4 v0 = __ldcg(&g_h1h[s0 * 8 + j]);
        uint4 v1 = __ldcg(&g_h1h[s1 * 8 + j]);
        u4acc(v0, a); u4acc(v1, a);
    } else if (i < cnt) {
        int s0 = __ldg(&g_adj[start + i]);
        u4acc(__ldcg(&g_h1h[s0 * 8 + j]), a);
    }
    phase_reduce(a);
    if (ph == 0) {
        float sc = g_norm[node];
        const float4* b4 = (const float4*)bias;
        float4 b0 = b4[j * 2], b1 = b4[j * 2 + 1];
        float4 o0, o1;
        o0.x = a[0].x * sc + b0.x;  o0.y = a[0].y * sc + b0.y;
        o0.z = a[1].x * sc + b0.z;  o0.w = a[1].y * sc + b0.w;
        o1.x = a[2].x * sc + b1.x;  o1.y = a[2].y * sc + b1.y;
        o1.z = a[3].x * sc + b1.z;  o1.w = a[3].y * sc + b1.w;
        float4* out4 = (float4*)out;
        out4[node * 16 + j * 2]     = o0;
        out4[node * 16 + j * 2 + 1] = o1;
    }
}

// ----------------------------------------------------------------------------
extern "C" void kernel_launch(void* const* d_in, const int* in_sizes, int n_in,
                              void* d_out, int out_size) {
    const int*   src    = (const int*)  d_in[0];
    const int*   dst    = (const int*)  d_in[1];
    const float* feat   = (const float*)d_in[2];
    const float* weight = (const float*)d_in[3];
    const float* bias   = (const float*)d_in[4];
    float*       out    = (float*)d_out;

    const int E = in_sizes[0];

    static cudaStream_t s2 = nullptr;
    static cudaEvent_t ev_fork = nullptr, ev_scan = nullptr, ev_join = nullptr;
    if (!s2) {
        cudaStreamCreateWithFlags(&s2, cudaStreamNonBlocking);
        cudaEventCreateWithFlags(&ev_fork, cudaEventDisableTiming);
        cudaEventCreateWithFlags(&ev_scan, cudaEventDisableTiming);
        cudaEventCreateWithFlags(&ev_join, cudaEventDisableTiming);
        cudaFuncSetAttribute(gemm_kernel,
                             cudaFuncAttributeMaxDynamicSharedMemorySize,
                             GEMM_SMEM_BYTES);
    }

    void* deg_ptr;
    cudaGetSymbolAddress(&deg_ptr, g_deg);

    cudaMemsetAsync(deg_ptr, 0, N_NODES * sizeof(int));

    // Fork GEMM immediately (no dependencies).
    cudaEventRecord(ev_fork, 0);
    cudaStreamWaitEvent(s2, ev_fork, 0);
    gemm_kernel<<<(N_NODES + 127) / 128, 256, GEMM_SMEM_BYTES, s2>>>(feat, weight);

    deg_kernel<<<(E / 4 + 255) / 256, 256>>>(dst, E);   // also sets bsum=-1
    scan_kernel<<<N_SCANB, SCAN_B>>>();                  // norm + row offsets

    // scale needs norm (scan, s0) + g0 (gemm, same stream); hidden behind fill
    cudaEventRecord(ev_scan, 0);
    cudaStreamWaitEvent(s2, ev_scan, 0);
    scale_kernel<<<(N_NODES * 8 + 255) / 256, 256, 0, s2>>>();
    cudaEventRecord(ev_join, s2);

    fill_kernel<<<(E + 255) / 256, 256>>>(src, dst, E);

    cudaStreamWaitEvent(0, ev_join, 0);

    int hop_threads = N_NODES * 32;
    int hop_blocks  = (hop_threads + 511) / 512;
    hop1_kernel<<<hop_blocks, 512>>>();
    hop2_kernel<<<hop_blocks, 512>>>(out, bias);
}